// round 2
// baseline (speedup 1.0000x reference)
#include <cuda_runtime.h>
#include <math.h>

#define BB 8
#define CH 64
#define HH 256
#define WW 256
#define HW 65536

// Scratch as device globals (no allocation allowed)
__device__ float g_h0[BB*CH*HW];      // encoded field (134 MB)
__device__ float g_v [BB*CH*64];      // projected modes [b][c][kxi*8+ky*2+{re,im}]
__device__ float g_gA[BB*CH*64];      // mode iteration ping
__device__ float g_gB[BB*CH*64];      // mode iteration pong
__device__ float g_Z [BB*HH*CH*8];    // per-row recon coeffs [b][h][c][f0,fr1,fi1,fr2,fi2,fr3,fi3,pad]
__device__ float g_wre[32*4096];      // repacked mix weights [slice][i*64+o]
__device__ float g_wim[32*4096];

// ---------------------------------------------------------------------------
// K0: repack spectral weights. slice s = kxi*4+ky; entry i*64+o.
// w1/w2 layout (i, o, mx, my) -> flat (i*64+o)*16 + mx*4 + my
// ---------------------------------------------------------------------------
__global__ void k_repack(const float* __restrict__ w1r, const float* __restrict__ w1i,
                         const float* __restrict__ w2r, const float* __restrict__ w2i)
{
    int s = blockIdx.x;
    int kxi = s >> 2, ky = s & 3;
    const float* srcr = (kxi < 4) ? w1r : w2r;
    const float* srci = (kxi < 4) ? w1i : w2i;
    int kk = (kxi & 3) * 4 + ky;
    for (int idx = threadIdx.x; idx < 4096; idx += blockDim.x) {
        g_wre[s*4096 + idx] = srcr[idx*16 + kk];
        g_wim[s*4096 + idx] = srci[idx*16 + kk];
    }
}

// ---------------------------------------------------------------------------
// K1: encoder  h0 = tanh(enc_w @ x + enc_b).  block=(w), grid=(h, b)
// ---------------------------------------------------------------------------
__global__ void k_encode(const float* __restrict__ x,
                         const float* __restrict__ ew,
                         const float* __restrict__ eb)
{
    __shared__ float sw[192];
    __shared__ float sb[64];
    int t = threadIdx.x;
    if (t < 192) sw[t] = ew[t];
    if (t < 64)  sb[t] = eb[t];
    __syncthreads();

    int w = t, h = blockIdx.x, b = blockIdx.y;
    const float* xp = x + ((b*3)*HH + h)*WW + w;
    float x0 = xp[0], x1 = xp[HW], x2 = xp[2*HW];
    float* hp = g_h0 + (b*CH*HH + h)*WW + w;
    #pragma unroll 8
    for (int c = 0; c < CH; c++) {
        float v = fmaf(sw[3*c], x0, fmaf(sw[3*c+1], x1, fmaf(sw[3*c+2], x2, sb[c])));
        hp[c*HW] = tanhf(v);
    }
}

// ---------------------------------------------------------------------------
// K2: projection v = P h0.  Per-thread column DFT over h (only kx=0..4 via
// Hermitian symmetry), then ky-phase combine + deterministic reduction over w.
// block=(w)=256, grid=(c, b)
// ---------------------------------------------------------------------------
__global__ void k_project()
{
    __shared__ float ph[256][8];   // per-h phases c1,s1,c2,s2,c3,s3,c4,s4
    __shared__ float red[8][64];   // per-warp partials
    int w = threadIdx.x, c = blockIdx.x, b = blockIdx.y;

    float a = 6.28318530717958647692f * (1.0f/256.0f) * (float)w;
    float c1, s1; sincosf(a, &s1, &c1);
    float c2 = c1*c1 - s1*s1,  s2 = 2.f*s1*c1;
    float c3 = c2*c1 - s2*s1,  s3 = s2*c1 + c2*s1;
    float c4 = c2*c2 - s2*s2,  s4 = 2.f*s2*c2;
    ph[w][0]=c1; ph[w][1]=s1; ph[w][2]=c2; ph[w][3]=s2;
    ph[w][4]=c3; ph[w][5]=s3; ph[w][6]=c4; ph[w][7]=s4;
    __syncthreads();

    const float* hp = g_h0 + (b*CH + c)*HW + w;
    float a0=0.f, ar1=0.f, b1=0.f, ar2=0.f, b2=0.f, ar3=0.f, b3=0.f, ar4=0.f, b4=0.f;
    #pragma unroll 4
    for (int hh = 0; hh < 256; hh++) {
        float v = hp[hh*256];
        float4 p0 = *(const float4*)&ph[hh][0];
        float4 p1 = *(const float4*)&ph[hh][4];
        a0 += v;
        ar1 = fmaf(v, p0.x, ar1);  b1 = fmaf(v, p0.y, b1);
        ar2 = fmaf(v, p0.z, ar2);  b2 = fmaf(v, p0.w, b2);
        ar3 = fmaf(v, p1.x, ar3);  b3 = fmaf(v, p1.y, b3);
        ar4 = fmaf(v, p1.z, ar4);  b4 = fmaf(v, p1.w, b4);
    }

    // column DFT values per kxi (kx map {0,1,2,3,252,253,254,255}); real input:
    // Col[k] = (ar_k, -b_k), Col[256-k] = conj(Col[k]) = (ar_k, +b_k)
    float crr[8] = {a0,  ar1, ar2, ar3, ar4, ar3, ar2, ar1};
    float cii[8] = {0.f, -b1, -b2, -b3,  b4,  b3,  b2,  b1};
    float cyk[4] = {1.f, c1, c2, c3};
    float syk[4] = {0.f, s1, s2, s3};

    int lane = w & 31, wid = w >> 5;
    #pragma unroll
    for (int kxi = 0; kxi < 8; kxi++) {
        #pragma unroll
        for (int ky = 0; ky < 4; ky++) {
            // (cr + i ci) * e^{-i ky th} = (cr + i ci)(cy - i sy)
            float re = crr[kxi]*cyk[ky] + cii[kxi]*syk[ky];
            float im = cii[kxi]*cyk[ky] - crr[kxi]*syk[ky];
            #pragma unroll
            for (int o = 16; o > 0; o >>= 1) {
                re += __shfl_xor_sync(0xffffffffu, re, o);
                im += __shfl_xor_sync(0xffffffffu, im, o);
            }
            if (lane == 0) {
                red[wid][(kxi*4+ky)*2    ] = re;
                red[wid][(kxi*4+ky)*2 + 1] = im;
            }
        }
    }
    __syncthreads();
    if (w < 64) {
        float s = 0.f;
        #pragma unroll
        for (int q = 0; q < 8; q++) s += red[q][w];
        g_v[(b*CH + c)*64 + w] = s;
    }
}

// ---------------------------------------------------------------------------
// K3: one mode-space iteration  g_next = g_prev + M(v + T g_prev)
// T = identity for ky>=1; at ky=0: (TG)[kx]=(G[kx]+conj(G[-kx]))/2 with the
// kx=252 conjugate partner (kx=4) truncated, kx=0 -> Re(G).
// block = 64 threads (o == i for the staging), grid = (kxi*4+ky, b)
// ---------------------------------------------------------------------------
__global__ void k_mix(int first, int odd)
{
    const float* gp = odd ? g_gB : g_gA;  // it even: prev=gA(unused when first), next=gB
    float*       gn = odd ? g_gA : g_gB;
    int o = threadIdx.x;
    int s = blockIdx.x;
    int kxi = s >> 2, ky = s & 3, b = blockIdx.y;

    __shared__ float fr[64], fi[64];
    {
        int i = o;
        int base = (b*CH + i)*64 + kxi*8 + ky*2;
        float vr = g_v[base], vi = g_v[base+1];
        float tr = 0.f, ti = 0.f;
        if (!first) {
            if (ky != 0)        { tr = gp[base];       ti = gp[base+1]; }
            else if (kxi == 0)  { tr = gp[base];       ti = 0.f; }
            else if (kxi == 4)  { tr = 0.5f*gp[base];  ti = 0.5f*gp[base+1]; }
            else {
                int pb = (b*CH + i)*64 + (8-kxi)*8 + ky*2;
                tr = 0.5f*(gp[base]   + gp[pb]);
                ti = 0.5f*(gp[base+1] - gp[pb+1]);
            }
        }
        fr[i] = vr + tr; fi[i] = vi + ti;
    }
    __syncthreads();

    const float* wre = g_wre + s*4096;
    const float* wim = g_wim + s*4096;
    float accr = 0.f, acci = 0.f;
    #pragma unroll 8
    for (int i = 0; i < 64; i++) {
        float wr_ = wre[i*64 + o], wi_ = wim[i*64 + o];
        float fre = fr[i], fim = fi[i];
        accr = fmaf(fre, wr_, accr); accr = fmaf(-fim, wi_, accr);
        acci = fmaf(fre, wi_, acci); acci = fmaf( fim, wr_, acci);
    }

    int obase = (b*CH + o)*64 + kxi*8 + ky*2;
    float g0r = 0.f, g0i = 0.f;
    if (!first) { g0r = gp[obase]; g0i = gp[obase+1]; }
    gn[obase]   = g0r + accr;
    gn[obase+1] = g0i + acci;
}

// ---------------------------------------------------------------------------
// K4: per-row reconstruction coefficients
// Z[h,ky] = sum_kx g6 e^{+2pi i kx h/256}; fold (1/H)(1/W) and the irfft
// factor-2 for ky>=1:  f0 = Re(Z0)/65536, (fr,fi)_ky = Z_ky/32768
// block=(h)=256, grid=(c, b)
// ---------------------------------------------------------------------------
__global__ void k_ztable()
{
    __shared__ float gm[64];
    int h = threadIdx.x, c = blockIdx.x, b = blockIdx.y;
    if (h < 64) gm[h] = g_gA[(b*CH + c)*64 + h];
    __syncthreads();

    float a = 6.28318530717958647692f * (1.0f/256.0f) * (float)h;
    float c1, s1; sincosf(a, &s1, &c1);
    float c2 = c1*c1 - s1*s1,  s2 = 2.f*s1*c1;
    float c3 = c2*c1 - s2*s1,  s3 = s2*c1 + c2*s1;
    float c4 = c2*c2 - s2*s2,  s4 = 2.f*s2*c2;
    // e^{+2pi i kx h/256}; kx=252..255 == e^{-2pi i (4,3,2,1) h/256}
    float pc[8] = {1.f, c1, c2, c3,  c4,  c3,  c2,  c1};
    float ps[8] = {0.f, s1, s2, s3, -s4, -s3, -s2, -s1};

    float outv[8];
    #pragma unroll
    for (int ky = 0; ky < 4; ky++) {
        float zr = 0.f, zi = 0.f;
        #pragma unroll
        for (int kxi = 0; kxi < 8; kxi++) {
            float gr = gm[kxi*8 + ky*2], gi = gm[kxi*8 + ky*2 + 1];
            zr += gr*pc[kxi] - gi*ps[kxi];
            zi += gr*ps[kxi] + gi*pc[kxi];
        }
        if (ky == 0) outv[0] = zr * (1.f/65536.f);
        else { outv[ky*2-1] = zr * (1.f/32768.f);
               outv[ky*2  ] = zi * (1.f/32768.f); }
    }
    outv[7] = 0.f;

    float* zp = g_Z + ((b*HH + h)*CH + c)*8;
    #pragma unroll
    for (int j = 0; j < 8; j++) zp[j] = outv[j];
}

// ---------------------------------------------------------------------------
// K5: fused epilogue.  hv = 2*h0 + recon; t = tanh(dec1 @ hv + b1);
// out = dec2 . t + b2.  hv staged per-thread in shared (dynamic-index safe).
// block=(w)=256, grid=(h, b). Dynamic smem: hv 64KB + w1^T 16KB + Z row 2KB.
// ---------------------------------------------------------------------------
#define FINAL_SMEM ((64*256 + 64*64 + 64*8) * 4)

__global__ void __launch_bounds__(256) k_final(
    const float* __restrict__ d1w, const float* __restrict__ d1b,
    const float* __restrict__ d2w, const float* __restrict__ d2b,
    float* __restrict__ out)
{
    extern __shared__ float sm[];
    float* hv   = sm;               // [c][tid]  (conflict-free by tid)
    float* sw1t = sm + 64*256;      // dec1_w transposed: [c][o]
    float* sz   = sw1t + 64*64;     // Z row: [c][8]
    __shared__ float sb1[64], sw2[64];

    int w = threadIdx.x, h = blockIdx.x, b = blockIdx.y;

    for (int idx = w; idx < 4096; idx += 256) {
        int o = idx >> 6, c = idx & 63;
        sw1t[c*64 + o] = d1w[idx];
    }
    if (w < 64) { sb1[w] = d1b[w]; sw2[w] = d2w[w]; }
    {
        const float* zp = g_Z + (b*HH + h)*CH*8;
        sz[w]       = zp[w];
        sz[w + 256] = zp[w + 256];
    }
    __syncthreads();

    float a = 6.28318530717958647692f * (1.0f/256.0f) * (float)w;
    float cy1, sy1; sincosf(a, &sy1, &cy1);
    float cy2 = cy1*cy1 - sy1*sy1, sy2 = 2.f*sy1*cy1;
    float cy3 = cy2*cy1 - sy2*sy1, sy3 = sy2*cy1 + cy2*sy1;

    const float* hp = g_h0 + b*CH*HW + h*WW + w;
    #pragma unroll 8
    for (int c = 0; c < 64; c++) {
        float4 z0 = *(const float4*)&sz[c*8];
        float4 z1 = *(const float4*)&sz[c*8 + 4];
        float r = fmaf(2.f, hp[c*HW], z0.x);
        r = fmaf(z0.y,  cy1, r); r = fmaf(z0.z, -sy1, r);
        r = fmaf(z0.w,  cy2, r); r = fmaf(z1.x, -sy2, r);
        r = fmaf(z1.y,  cy3, r); r = fmaf(z1.z, -sy3, r);
        hv[c*256 + w] = r;   // same-thread readback below: no sync needed
    }

    float outacc = d2b[0];
    #pragma unroll
    for (int ch = 0; ch < 4; ch++) {
        float acc[16];
        #pragma unroll
        for (int k = 0; k < 16; k++) acc[k] = sb1[ch*16 + k];
        #pragma unroll 16
        for (int c = 0; c < 64; c++) {
            float hvv = hv[c*256 + w];
            const float4* wp = (const float4*)&sw1t[c*64 + ch*16];
            float4 w0 = wp[0], w1 = wp[1], w2 = wp[2], w3 = wp[3];
            acc[0]  = fmaf(hvv, w0.x, acc[0]);  acc[1]  = fmaf(hvv, w0.y, acc[1]);
            acc[2]  = fmaf(hvv, w0.z, acc[2]);  acc[3]  = fmaf(hvv, w0.w, acc[3]);
            acc[4]  = fmaf(hvv, w1.x, acc[4]);  acc[5]  = fmaf(hvv, w1.y, acc[5]);
            acc[6]  = fmaf(hvv, w1.z, acc[6]);  acc[7]  = fmaf(hvv, w1.w, acc[7]);
            acc[8]  = fmaf(hvv, w2.x, acc[8]);  acc[9]  = fmaf(hvv, w2.y, acc[9]);
            acc[10] = fmaf(hvv, w2.z, acc[10]); acc[11] = fmaf(hvv, w2.w, acc[11]);
            acc[12] = fmaf(hvv, w3.x, acc[12]); acc[13] = fmaf(hvv, w3.y, acc[13]);
            acc[14] = fmaf(hvv, w3.z, acc[14]); acc[15] = fmaf(hvv, w3.w, acc[15]);
        }
        #pragma unroll
        for (int k = 0; k < 16; k++)
            outacc = fmaf(tanhf(acc[k]), sw2[ch*16 + k], outacc);
    }
    out[b*HW + h*WW + w] = outacc;
}

extern "C" void kernel_launch(void* const* d_in, const int* in_sizes, int n_in,
                              void* d_out, int out_size)
{
    const float* x   = (const float*)d_in[0];
    const float* ew  = (const float*)d_in[1];
    const float* eb  = (const float*)d_in[2];
    const float* d1w = (const float*)d_in[3];
    const float* d1b = (const float*)d_in[4];
    const float* d2w = (const float*)d_in[5];
    const float* d2b = (const float*)d_in[6];
    const float* w1r = (const float*)d_in[7];
    const float* w1i = (const float*)d_in[8];
    const float* w2r = (const float*)d_in[9];
    const float* w2i = (const float*)d_in[10];
    float* out = (float*)d_out;

    cudaFuncSetAttribute(k_final, cudaFuncAttributeMaxDynamicSharedMemorySize, FINAL_SMEM);

    k_repack<<<32, 256>>>(w1r, w1i, w2r, w2i);
    k_encode<<<dim3(256, 8), 256>>>(x, ew, eb);
    k_project<<<dim3(64, 8), 256>>>();
    for (int it = 0; it < 6; it++)
        k_mix<<<dim3(32, 8), 64>>>(it == 0 ? 1 : 0, it & 1);
    k_ztable<<<dim3(64, 8), 256>>>();
    k_final<<<dim3(256, 8), 256, FINAL_SMEM>>>(d1w, d1b, d2w, d2b, out);
}

// round 3
// speedup vs baseline: 1.0254x; 1.0254x over previous
#include <cuda_runtime.h>
#include <math.h>

#define BB 8
#define CH 64
#define HH 256
#define WW 256
#define HW 65536

typedef unsigned long long u64;

__device__ __forceinline__ u64 pk2(float lo, float hi){ u64 r; asm("mov.b64 %0,{%1,%2};" : "=l"(r) : "f"(lo), "f"(hi)); return r; }
__device__ __forceinline__ u64 splat2(float v){ u64 r; asm("mov.b64 %0,{%1,%1};" : "=l"(r) : "f"(v)); return r; }
__device__ __forceinline__ float2 upk2(u64 a){ float2 f; asm("mov.b64 {%0,%1},%2;" : "=f"(f.x), "=f"(f.y) : "l"(a)); return f; }
__device__ __forceinline__ u64 f2fma(u64 a, u64 b, u64 c){ u64 d; asm("fma.rn.f32x2 %0,%1,%2,%3;" : "=l"(d) : "l"(a), "l"(b), "l"(c)); return d; }
__device__ __forceinline__ u64 f2add(u64 a, u64 b){ u64 d; asm("add.rn.f32x2 %0,%1,%2;" : "=l"(d) : "l"(a), "l"(b)); return d; }

// Scratch (device globals: no allocation allowed)
__device__ float g_h0[BB*CH*HW];      // 2*tanh(enc) field (134 MB)
__device__ float g_v [BB*CH*64];      // projected modes [b][c][kxi*8+ky*2+{re,im}]
__device__ float g_gA[BB*CH*64];      // final mode state after 6 iterations
__device__ float g_Z [BB*HH*CH*8];    // per-row recon coeffs [b][h][c][f0,fr1,fi1,fr2,fi2,fr3,fi3,pad]
__device__ float g_wre[32*4096];      // repacked mix weights [slice][i*64+o]
__device__ float g_wim[32*4096];

// ---------------------------------------------------------------------------
// K0: repack spectral weights. slice s = kxi*4+ky; entry i*64+o.
// ---------------------------------------------------------------------------
__global__ void k_repack(const float* __restrict__ w1r, const float* __restrict__ w1i,
                         const float* __restrict__ w2r, const float* __restrict__ w2i)
{
    int s = blockIdx.x;
    int kxi = s >> 2, ky = s & 3;
    const float* srcr = (kxi < 4) ? w1r : w2r;
    const float* srci = (kxi < 4) ? w1i : w2i;
    int kk = (kxi & 3) * 4 + ky;
    for (int idx = threadIdx.x; idx < 4096; idx += blockDim.x) {
        g_wre[s*4096 + idx] = srcr[idx*16 + kk];
        g_wim[s*4096 + idx] = srci[idx*16 + kk];
    }
}

// ---------------------------------------------------------------------------
// K1: encoder  h0 = 2*tanh(enc_w @ x + enc_b)   (skip 2x folded here)
// ---------------------------------------------------------------------------
__global__ void k_encode(const float* __restrict__ x,
                         const float* __restrict__ ew,
                         const float* __restrict__ eb)
{
    __shared__ float sw[192];
    __shared__ float sb[64];
    int t = threadIdx.x;
    if (t < 192) sw[t] = ew[t];
    if (t < 64)  sb[t] = eb[t];
    __syncthreads();

    int w = t, h = blockIdx.x, b = blockIdx.y;
    const float* xp = x + ((b*3)*HH + h)*WW + w;
    float x0 = xp[0], x1 = xp[HW], x2 = xp[2*HW];
    float* hp = g_h0 + (b*CH*HH + h)*WW + w;
    #pragma unroll 8
    for (int c = 0; c < CH; c++) {
        float v = fmaf(sw[3*c], x0, fmaf(sw[3*c+1], x1, fmaf(sw[3*c+2], x2, sb[c])));
        hp[c*HW] = 2.f * tanhf(v);
    }
}

// ---------------------------------------------------------------------------
// K2: projection v = P h0 (scaled 2x since h0 is doubled; folded out in K4).
// ---------------------------------------------------------------------------
__global__ void k_project()
{
    __shared__ float ph[256][8];
    __shared__ float red[8][64];
    int w = threadIdx.x, c = blockIdx.x, b = blockIdx.y;

    float a = 6.28318530717958647692f * (1.0f/256.0f) * (float)w;
    float c1, s1; sincosf(a, &s1, &c1);
    float c2 = c1*c1 - s1*s1,  s2 = 2.f*s1*c1;
    float c3 = c2*c1 - s2*s1,  s3 = s2*c1 + c2*s1;
    float c4 = c2*c2 - s2*s2,  s4 = 2.f*s2*c2;
    ph[w][0]=c1; ph[w][1]=s1; ph[w][2]=c2; ph[w][3]=s2;
    ph[w][4]=c3; ph[w][5]=s3; ph[w][6]=c4; ph[w][7]=s4;
    __syncthreads();

    const float* hp = g_h0 + (b*CH + c)*HW + w;
    float a0=0.f, ar1=0.f, b1=0.f, ar2=0.f, b2=0.f, ar3=0.f, b3=0.f, ar4=0.f, b4=0.f;
    #pragma unroll 4
    for (int hh = 0; hh < 256; hh++) {
        float v = hp[hh*256];
        float4 p0 = *(const float4*)&ph[hh][0];
        float4 p1 = *(const float4*)&ph[hh][4];
        a0 += v;
        ar1 = fmaf(v, p0.x, ar1);  b1 = fmaf(v, p0.y, b1);
        ar2 = fmaf(v, p0.z, ar2);  b2 = fmaf(v, p0.w, b2);
        ar3 = fmaf(v, p1.x, ar3);  b3 = fmaf(v, p1.y, b3);
        ar4 = fmaf(v, p1.z, ar4);  b4 = fmaf(v, p1.w, b4);
    }

    float crr[8] = {a0,  ar1, ar2, ar3, ar4, ar3, ar2, ar1};
    float cii[8] = {0.f, -b1, -b2, -b3,  b4,  b3,  b2,  b1};
    float cyk[4] = {1.f, c1, c2, c3};
    float syk[4] = {0.f, s1, s2, s3};

    int lane = w & 31, wid = w >> 5;
    #pragma unroll
    for (int kxi = 0; kxi < 8; kxi++) {
        #pragma unroll
        for (int ky = 0; ky < 4; ky++) {
            float re = crr[kxi]*cyk[ky] + cii[kxi]*syk[ky];
            float im = cii[kxi]*cyk[ky] - crr[kxi]*syk[ky];
            #pragma unroll
            for (int o = 16; o > 0; o >>= 1) {
                re += __shfl_xor_sync(0xffffffffu, re, o);
                im += __shfl_xor_sync(0xffffffffu, im, o);
            }
            if (lane == 0) {
                red[wid][(kxi*4+ky)*2    ] = re;
                red[wid][(kxi*4+ky)*2 + 1] = im;
            }
        }
    }
    __syncthreads();
    if (w < 64) {
        float s = 0.f;
        #pragma unroll
        for (int q = 0; q < 8; q++) s += red[q][w];
        g_v[(b*CH + c)*64 + w] = s;
    }
}

// ---------------------------------------------------------------------------
// K3: ALL 6 mode-space iterations fused.  g_{n+1} = g_n + M(v + T g_n).
// Coupling only at ky=0 between kxi pairs {1,7},{2,6},{3,5}; {0},{4} are
// self-coupled; ky>=1 slices are independent (T = identity).
// grid = (29 groups, 8 batches), block = 128 (2 slices x 64 outputs).
// Weights staged in dynamic smem ONCE (64 KB), iterations internal.
// ---------------------------------------------------------------------------
__global__ void __launch_bounds__(128) k_mix6()
{
    extern __shared__ float smw[];
    float* swr = smw;          // [2][4096]
    float* swi = smw + 8192;
    __shared__ float vr[2][64], vi[2][64], gr[2][64], gi[2][64], fr[2][64], fi[2][64];

    int g = blockIdx.x, b = blockIdx.y, tid = threadIdx.x;
    int s0, s1 = -1, tmode;
    if (g < 24)      { int kxi=g/3, ky=g%3+1; s0=kxi*4+ky; tmode=0; }
    else if (g==24)  { s0=0;           tmode=1; }
    else if (g==25)  { s0=16;          tmode=2; }
    else if (g==26)  { s0=4;  s1=28;   tmode=3; }
    else if (g==27)  { s0=8;  s1=24;   tmode=3; }
    else             { s0=12; s1=20;   tmode=3; }
    int nsl = (s1 >= 0) ? 2 : 1;

    for (int q = 0; q < nsl; q++) {
        int s = q ? s1 : s0;
        for (int idx = tid; idx < 4096; idx += 128) {
            swr[q*4096 + idx] = g_wre[s*4096 + idx];
            swi[q*4096 + idx] = g_wim[s*4096 + idx];
        }
    }
    int sl = tid >> 6, o = tid & 63;
    if (sl < nsl) {
        int s = sl ? s1 : s0;
        int base = (b*64 + o)*64 + s*2;
        vr[sl][o] = g_v[base]; vi[sl][o] = g_v[base+1];
    }
    __syncthreads();

    for (int it = 0; it < 6; it++) {
        if (sl < nsl) {
            float tr = 0.f, ti = 0.f;
            if (it > 0) {
                float grv = gr[sl][o], giv = gi[sl][o];
                if      (tmode == 0) { tr = grv;       ti = giv; }
                else if (tmode == 1) { tr = grv;       ti = 0.f; }
                else if (tmode == 2) { tr = 0.5f*grv;  ti = 0.5f*giv; }
                else { tr = 0.5f*(grv + gr[1-sl][o]);  ti = 0.5f*(giv - gi[1-sl][o]); }
            }
            fr[sl][o] = vr[sl][o] + tr;
            fi[sl][o] = vi[sl][o] + ti;
        }
        __syncthreads();
        float accr = 0.f, acci = 0.f;
        if (sl < nsl) {
            const float* wrp = swr + sl*4096;
            const float* wip = swi + sl*4096;
            #pragma unroll 8
            for (int i = 0; i < 64; i++) {
                float w_r = wrp[i*64 + o], w_i = wip[i*64 + o];
                float f_r = fr[sl][i],     f_i = fi[sl][i];
                accr = fmaf(f_r, w_r, accr); accr = fmaf(-f_i, w_i, accr);
                acci = fmaf(f_r, w_i, acci); acci = fmaf( f_i, w_r, acci);
            }
        }
        __syncthreads();
        if (sl < nsl) {
            float g0r = it ? gr[sl][o] : 0.f;
            float g0i = it ? gi[sl][o] : 0.f;
            gr[sl][o] = g0r + accr;
            gi[sl][o] = g0i + acci;
        }
        __syncthreads();
    }

    if (sl < nsl) {
        int s = sl ? s1 : s0;
        int base = (b*64 + o)*64 + s*2;
        g_gA[base]   = gr[sl][o];
        g_gA[base+1] = gi[sl][o];
    }
}

// ---------------------------------------------------------------------------
// K4: per-row reconstruction coefficients. Extra 0.5 folded in because h0 is
// stored doubled (so v, g, Z are doubled).
// ---------------------------------------------------------------------------
__global__ void k_ztable()
{
    __shared__ float gm[64];
    int h = threadIdx.x, c = blockIdx.x, b = blockIdx.y;
    if (h < 64) gm[h] = g_gA[(b*CH + c)*64 + h];
    __syncthreads();

    float a = 6.28318530717958647692f * (1.0f/256.0f) * (float)h;
    float c1, s1; sincosf(a, &s1, &c1);
    float c2 = c1*c1 - s1*s1,  s2 = 2.f*s1*c1;
    float c3 = c2*c1 - s2*s1,  s3 = s2*c1 + c2*s1;
    float c4 = c2*c2 - s2*s2,  s4 = 2.f*s2*c2;
    float pc[8] = {1.f, c1, c2, c3,  c4,  c3,  c2,  c1};
    float ps[8] = {0.f, s1, s2, s3, -s4, -s3, -s2, -s1};

    float outv[8];
    #pragma unroll
    for (int ky = 0; ky < 4; ky++) {
        float zr = 0.f, zi = 0.f;
        #pragma unroll
        for (int kxi = 0; kxi < 8; kxi++) {
            float grv = gm[kxi*8 + ky*2], giv = gm[kxi*8 + ky*2 + 1];
            zr += grv*pc[kxi] - giv*ps[kxi];
            zi += grv*ps[kxi] + giv*pc[kxi];
        }
        if (ky == 0) outv[0] = zr * (1.f/131072.f);
        else { outv[ky*2-1] = zr * (1.f/65536.f);
               outv[ky*2  ] = zi * (1.f/65536.f); }
    }
    outv[7] = 0.f;

    float* zp = g_Z + ((b*HH + h)*CH + c)*8;
    #pragma unroll
    for (int j = 0; j < 8; j++) zp[j] = outv[j];
}

// ---------------------------------------------------------------------------
// K5: fused epilogue with fma.rn.f32x2 (2x fp32 throughput).
// Block = 128 threads, 4 pixels/thread (two f32x2 lanes), two rows per block.
// hv staged fp32 in dynamic smem; dec1 = 32 packed-acc register GEMV.
// grid = (128, 8).
// ---------------------------------------------------------------------------
#define FINAL_SMEM (131072 + 8192 + 16384)

__global__ void __launch_bounds__(128) k_final(
    const float* __restrict__ d1w, const float* __restrict__ d1b,
    const float* __restrict__ d2w, const float* __restrict__ d2b,
    float* __restrict__ out)
{
    extern __shared__ char smc[];
    u64*   hv   = (u64*)smc;                       // [2][64][64][2] u64 = 128 KB
    u64*   zsm  = (u64*)(smc + 131072);            // [2][64][8] splatted = 8 KB
    float* sw1t = (float*)(smc + 131072 + 8192);   // dec1_w^T [c][o] = 16 KB
    __shared__ float sb1[64], sw2[64];

    int t = threadIdx.x, b = blockIdx.y;
    int hbase = blockIdx.x * 2;
    int row = t >> 6, tl = t & 63;
    int h = hbase + row, w0 = tl * 4;

    for (int idx = t; idx < 4096; idx += 128)
        sw1t[(idx & 63)*64 + (idx >> 6)] = d1w[idx];
    if (t < 64) { sb1[t] = d1b[t]; sw2[t] = d2w[t]; }
    {
        const float* zrow = g_Z + (b*HH + hbase)*CH*8;  // two rows contiguous
        for (int idx = t; idx < 1024; idx += 128) {
            int j = idx & 7;
            float v = zrow[idx];
            if (j == 2 || j == 4 || j == 6) v = -v;
            if (j == 7) v = 0.f;
            zsm[idx] = splat2(v);
        }
    }
    __syncthreads();

    // phases for the 4 pixels
    float cc[4][3], ss[4][3];
    #pragma unroll
    for (int q = 0; q < 4; q++) {
        float a = 6.28318530717958647692f * (1.0f/256.0f) * (float)(w0 + q);
        float c1, s1; sincosf(a, &s1, &c1);
        float c2 = c1*c1 - s1*s1, s2 = 2.f*s1*c1;
        float c3 = c2*c1 - s2*s1, s3 = s2*c1 + c2*s1;
        cc[q][0]=c1; cc[q][1]=c2; cc[q][2]=c3;
        ss[q][0]=s1; ss[q][1]=s2; ss[q][2]=s3;
    }
    u64 Pc_a[3], Pc_b[3], Ps_a[3], Ps_b[3];
    #pragma unroll
    for (int k = 0; k < 3; k++) {
        Pc_a[k] = pk2(cc[0][k], cc[1][k]);  Pc_b[k] = pk2(cc[2][k], cc[3][k]);
        Ps_a[k] = pk2(ss[0][k], ss[1][k]);  Ps_b[k] = pk2(ss[2][k], ss[3][k]);
    }

    // recon: hv = h0(doubled) + sum of 6 packed FMAs
    const float* h0p = g_h0 + (b*CH)*HW + h*WW + w0;
    #pragma unroll 4
    for (int c = 0; c < 64; c++) {
        float4 h4 = *(const float4*)(h0p + c*HW);
        const u64* zp = zsm + (row*64 + c)*8;
        ulonglong2 z01 = *(const ulonglong2*)(zp);
        ulonglong2 z23 = *(const ulonglong2*)(zp + 2);
        ulonglong2 z45 = *(const ulonglong2*)(zp + 4);
        u64 z6 = zp[6];
        u64 ra = f2add(pk2(h4.x, h4.y), z01.x);
        u64 rb = f2add(pk2(h4.z, h4.w), z01.x);
        ra = f2fma(z01.y, Pc_a[0], ra);  rb = f2fma(z01.y, Pc_b[0], rb);
        ra = f2fma(z23.x, Ps_a[0], ra);  rb = f2fma(z23.x, Ps_b[0], rb);
        ra = f2fma(z23.y, Pc_a[1], ra);  rb = f2fma(z23.y, Pc_b[1], rb);
        ra = f2fma(z45.x, Ps_a[1], ra);  rb = f2fma(z45.x, Ps_b[1], rb);
        ra = f2fma(z45.y, Pc_a[2], ra);  rb = f2fma(z45.y, Pc_b[2], rb);
        ra = f2fma(z6,    Ps_a[2], ra);  rb = f2fma(z6,    Ps_b[2], rb);
        *(ulonglong2*)&hv[((row*64 + c)*64 + tl)*2] = make_ulonglong2(ra, rb);
    }
    // hv written and read by the same thread only: no sync needed

    u64 oacc_a = splat2(0.f), oacc_b = splat2(0.f);
    #pragma unroll 1
    for (int ch = 0; ch < 4; ch++) {
        u64 acc_a[16], acc_b[16];
        #pragma unroll
        for (int k = 0; k < 16; k++) { u64 bb = splat2(sb1[ch*16 + k]); acc_a[k] = bb; acc_b[k] = bb; }
        #pragma unroll 8
        for (int c = 0; c < 64; c++) {
            ulonglong2 hp2 = *(const ulonglong2*)&hv[((row*64 + c)*64 + tl)*2];
            const float4* wq = (const float4*)&sw1t[c*64 + ch*16];
            #pragma unroll
            for (int k4 = 0; k4 < 4; k4++) {
                float4 wv = wq[k4];
                u64 ws;
                ws = splat2(wv.x); acc_a[k4*4+0] = f2fma(hp2.x, ws, acc_a[k4*4+0]); acc_b[k4*4+0] = f2fma(hp2.y, ws, acc_b[k4*4+0]);
                ws = splat2(wv.y); acc_a[k4*4+1] = f2fma(hp2.x, ws, acc_a[k4*4+1]); acc_b[k4*4+1] = f2fma(hp2.y, ws, acc_b[k4*4+1]);
                ws = splat2(wv.z); acc_a[k4*4+2] = f2fma(hp2.x, ws, acc_a[k4*4+2]); acc_b[k4*4+2] = f2fma(hp2.y, ws, acc_b[k4*4+2]);
                ws = splat2(wv.w); acc_a[k4*4+3] = f2fma(hp2.x, ws, acc_a[k4*4+3]); acc_b[k4*4+3] = f2fma(hp2.y, ws, acc_b[k4*4+3]);
            }
        }
        #pragma unroll
        for (int k = 0; k < 16; k++) {
            float2 va = upk2(acc_a[k]);
            float2 vb = upk2(acc_b[k]);
            u64 ta = pk2(tanhf(va.x), tanhf(va.y));
            u64 tb = pk2(tanhf(vb.x), tanhf(vb.y));
            u64 w2s = splat2(sw2[ch*16 + k]);
            oacc_a = f2fma(ta, w2s, oacc_a);
            oacc_b = f2fma(tb, w2s, oacc_b);
        }
    }
    float2 oa = upk2(oacc_a), ob = upk2(oacc_b);
    float b2v = d2b[0];
    float4 res = make_float4(oa.x + b2v, oa.y + b2v, ob.x + b2v, ob.y + b2v);
    *(float4*)(out + b*HW + h*WW + w0) = res;
}

extern "C" void kernel_launch(void* const* d_in, const int* in_sizes, int n_in,
                              void* d_out, int out_size)
{
    const float* x   = (const float*)d_in[0];
    const float* ew  = (const float*)d_in[1];
    const float* eb  = (const float*)d_in[2];
    const float* d1w = (const float*)d_in[3];
    const float* d1b = (const float*)d_in[4];
    const float* d2w = (const float*)d_in[5];
    const float* d2b = (const float*)d_in[6];
    const float* w1r = (const float*)d_in[7];
    const float* w1i = (const float*)d_in[8];
    const float* w2r = (const float*)d_in[9];
    const float* w2i = (const float*)d_in[10];
    float* out = (float*)d_out;

    cudaFuncSetAttribute(k_mix6, cudaFuncAttributeMaxDynamicSharedMemorySize, 65536);
    cudaFuncSetAttribute(k_final, cudaFuncAttributeMaxDynamicSharedMemorySize, FINAL_SMEM);

    k_repack<<<32, 256>>>(w1r, w1i, w2r, w2i);
    k_encode<<<dim3(256, 8), 256>>>(x, ew, eb);
    k_project<<<dim3(64, 8), 256>>>();
    k_mix6<<<dim3(29, 8), 128, 65536>>>();
    k_ztable<<<dim3(64, 8), 256>>>();
    k_final<<<dim3(128, 8), 128, FINAL_SMEM>>>(d1w, d1b, d2w, d2b, out);
}

// round 4
// speedup vs baseline: 1.1328x; 1.1047x over previous
#include <cuda_runtime.h>
#include <math.h>

#define BB 8
#define CH 64
#define HH 256
#define WW 256
#define HW 65536

typedef unsigned long long u64;

__device__ __forceinline__ u64 pk2(float lo, float hi){ u64 r; asm("mov.b64 %0,{%1,%2};" : "=l"(r) : "f"(lo), "f"(hi)); return r; }
__device__ __forceinline__ u64 splat2(float v){ u64 r; asm("mov.b64 %0,{%1,%1};" : "=l"(r) : "f"(v)); return r; }
__device__ __forceinline__ float2 upk2(u64 a){ float2 f; asm("mov.b64 {%0,%1},%2;" : "=f"(f.x), "=f"(f.y) : "l"(a)); return f; }
__device__ __forceinline__ u64 f2fma(u64 a, u64 b, u64 c){ u64 d; asm("fma.rn.f32x2 %0,%1,%2,%3;" : "=l"(d) : "l"(a), "l"(b), "l"(c)); return d; }

// Scratch (device globals: no allocation allowed)
__device__ float g_h0[BB*CH*HW];      // 2*tanh(enc) field (134 MB)
__device__ float g_v [BB*CH*64];      // projected modes [b][c][kxi*8+ky*2+{re,im}]
__device__ float g_gA[BB*CH*64];      // final mode state after 6 iterations
__device__ float g_Z [BB*HH*CH*8];    // per-row recon coeffs [b][h][c][f0,fr1,fi1,fr2,fi2,fr3,fi3,pad]
__device__ float g_wre[32*4096];      // repacked mix weights [slice][i*64+o]
__device__ float g_wim[32*4096];

// ---------------------------------------------------------------------------
// K0: repack spectral weights. slice s = kxi*4+ky; entry i*64+o.
// ---------------------------------------------------------------------------
__global__ void k_repack(const float* __restrict__ w1r, const float* __restrict__ w1i,
                         const float* __restrict__ w2r, const float* __restrict__ w2i)
{
    int s = blockIdx.x;
    int kxi = s >> 2, ky = s & 3;
    const float* srcr = (kxi < 4) ? w1r : w2r;
    const float* srci = (kxi < 4) ? w1i : w2i;
    int kk = (kxi & 3) * 4 + ky;
    for (int idx = threadIdx.x; idx < 4096; idx += blockDim.x) {
        g_wre[s*4096 + idx] = srcr[idx*16 + kk];
        g_wim[s*4096 + idx] = srci[idx*16 + kk];
    }
}

// ---------------------------------------------------------------------------
// K1: encoder  h0 = 2*tanh(enc_w @ x + enc_b)   (skip 2x folded here)
// ---------------------------------------------------------------------------
__global__ void k_encode(const float* __restrict__ x,
                         const float* __restrict__ ew,
                         const float* __restrict__ eb)
{
    __shared__ float sw[192];
    __shared__ float sb[64];
    int t = threadIdx.x;
    if (t < 192) sw[t] = ew[t];
    if (t < 64)  sb[t] = eb[t];
    __syncthreads();

    int w = t, h = blockIdx.x, b = blockIdx.y;
    const float* xp = x + ((b*3)*HH + h)*WW + w;
    float x0 = xp[0], x1 = xp[HW], x2 = xp[2*HW];
    float* hp = g_h0 + (b*CH*HH + h)*WW + w;
    #pragma unroll 8
    for (int c = 0; c < CH; c++) {
        float v = fmaf(sw[3*c], x0, fmaf(sw[3*c+1], x1, fmaf(sw[3*c+2], x2, sb[c])));
        hp[c*HW] = 2.f * tanhf(v);
    }
}

// ---------------------------------------------------------------------------
// K2: projection v = P h0 (scaled 2x since h0 is doubled; folded out in K4).
// ---------------------------------------------------------------------------
__global__ void k_project()
{
    __shared__ float ph[256][8];
    __shared__ float red[8][64];
    int w = threadIdx.x, c = blockIdx.x, b = blockIdx.y;

    float a = 6.28318530717958647692f * (1.0f/256.0f) * (float)w;
    float c1, s1; sincosf(a, &s1, &c1);
    float c2 = c1*c1 - s1*s1,  s2 = 2.f*s1*c1;
    float c3 = c2*c1 - s2*s1,  s3 = s2*c1 + c2*s1;
    float c4 = c2*c2 - s2*s2,  s4 = 2.f*s2*c2;
    ph[w][0]=c1; ph[w][1]=s1; ph[w][2]=c2; ph[w][3]=s2;
    ph[w][4]=c3; ph[w][5]=s3; ph[w][6]=c4; ph[w][7]=s4;
    __syncthreads();

    const float* hp = g_h0 + (b*CH + c)*HW + w;
    float a0=0.f, ar1=0.f, b1=0.f, ar2=0.f, b2=0.f, ar3=0.f, b3=0.f, ar4=0.f, b4=0.f;
    #pragma unroll 4
    for (int hh = 0; hh < 256; hh++) {
        float v = hp[hh*256];
        float4 p0 = *(const float4*)&ph[hh][0];
        float4 p1 = *(const float4*)&ph[hh][4];
        a0 += v;
        ar1 = fmaf(v, p0.x, ar1);  b1 = fmaf(v, p0.y, b1);
        ar2 = fmaf(v, p0.z, ar2);  b2 = fmaf(v, p0.w, b2);
        ar3 = fmaf(v, p1.x, ar3);  b3 = fmaf(v, p1.y, b3);
        ar4 = fmaf(v, p1.z, ar4);  b4 = fmaf(v, p1.w, b4);
    }

    float crr[8] = {a0,  ar1, ar2, ar3, ar4, ar3, ar2, ar1};
    float cii[8] = {0.f, -b1, -b2, -b3,  b4,  b3,  b2,  b1};
    float cyk[4] = {1.f, c1, c2, c3};
    float syk[4] = {0.f, s1, s2, s3};

    int lane = w & 31, wid = w >> 5;
    #pragma unroll
    for (int kxi = 0; kxi < 8; kxi++) {
        #pragma unroll
        for (int ky = 0; ky < 4; ky++) {
            float re = crr[kxi]*cyk[ky] + cii[kxi]*syk[ky];
            float im = cii[kxi]*cyk[ky] - crr[kxi]*syk[ky];
            #pragma unroll
            for (int o = 16; o > 0; o >>= 1) {
                re += __shfl_xor_sync(0xffffffffu, re, o);
                im += __shfl_xor_sync(0xffffffffu, im, o);
            }
            if (lane == 0) {
                red[wid][(kxi*4+ky)*2    ] = re;
                red[wid][(kxi*4+ky)*2 + 1] = im;
            }
        }
    }
    __syncthreads();
    if (w < 64) {
        float s = 0.f;
        #pragma unroll
        for (int q = 0; q < 8; q++) s += red[q][w];
        g_v[(b*CH + c)*64 + w] = s;
    }
}

// ---------------------------------------------------------------------------
// K3: ALL 6 mode-space iterations fused.
// ---------------------------------------------------------------------------
__global__ void __launch_bounds__(128) k_mix6()
{
    extern __shared__ float smw[];
    float* swr = smw;          // [2][4096]
    float* swi = smw + 8192;
    __shared__ float vr[2][64], vi[2][64], gr[2][64], gi[2][64], fr[2][64], fi[2][64];

    int g = blockIdx.x, b = blockIdx.y, tid = threadIdx.x;
    int s0, s1 = -1, tmode;
    if (g < 24)      { int kxi=g/3, ky=g%3+1; s0=kxi*4+ky; tmode=0; }
    else if (g==24)  { s0=0;           tmode=1; }
    else if (g==25)  { s0=16;          tmode=2; }
    else if (g==26)  { s0=4;  s1=28;   tmode=3; }
    else if (g==27)  { s0=8;  s1=24;   tmode=3; }
    else             { s0=12; s1=20;   tmode=3; }
    int nsl = (s1 >= 0) ? 2 : 1;

    for (int q = 0; q < nsl; q++) {
        int s = q ? s1 : s0;
        for (int idx = tid; idx < 4096; idx += 128) {
            swr[q*4096 + idx] = g_wre[s*4096 + idx];
            swi[q*4096 + idx] = g_wim[s*4096 + idx];
        }
    }
    int sl = tid >> 6, o = tid & 63;
    if (sl < nsl) {
        int s = sl ? s1 : s0;
        int base = (b*64 + o)*64 + s*2;
        vr[sl][o] = g_v[base]; vi[sl][o] = g_v[base+1];
    }
    __syncthreads();

    for (int it = 0; it < 6; it++) {
        if (sl < nsl) {
            float tr = 0.f, ti = 0.f;
            if (it > 0) {
                float grv = gr[sl][o], giv = gi[sl][o];
                if      (tmode == 0) { tr = grv;       ti = giv; }
                else if (tmode == 1) { tr = grv;       ti = 0.f; }
                else if (tmode == 2) { tr = 0.5f*grv;  ti = 0.5f*giv; }
                else { tr = 0.5f*(grv + gr[1-sl][o]);  ti = 0.5f*(giv - gi[1-sl][o]); }
            }
            fr[sl][o] = vr[sl][o] + tr;
            fi[sl][o] = vi[sl][o] + ti;
        }
        __syncthreads();
        float accr = 0.f, acci = 0.f;
        if (sl < nsl) {
            const float* wrp = swr + sl*4096;
            const float* wip = swi + sl*4096;
            #pragma unroll 8
            for (int i = 0; i < 64; i++) {
                float w_r = wrp[i*64 + o], w_i = wip[i*64 + o];
                float f_r = fr[sl][i],     f_i = fi[sl][i];
                accr = fmaf(f_r, w_r, accr); accr = fmaf(-f_i, w_i, accr);
                acci = fmaf(f_r, w_i, acci); acci = fmaf( f_i, w_r, acci);
            }
        }
        __syncthreads();
        if (sl < nsl) {
            float g0r = it ? gr[sl][o] : 0.f;
            float g0i = it ? gi[sl][o] : 0.f;
            gr[sl][o] = g0r + accr;
            gi[sl][o] = g0i + acci;
        }
        __syncthreads();
    }

    if (sl < nsl) {
        int s = sl ? s1 : s0;
        int base = (b*64 + o)*64 + s*2;
        g_gA[base]   = gr[sl][o];
        g_gA[base+1] = gi[sl][o];
    }
}

// ---------------------------------------------------------------------------
// K4: per-row reconstruction coefficients (0.5 folded for doubled h0).
// ---------------------------------------------------------------------------
__global__ void k_ztable()
{
    __shared__ float gm[64];
    int h = threadIdx.x, c = blockIdx.x, b = blockIdx.y;
    if (h < 64) gm[h] = g_gA[(b*CH + c)*64 + h];
    __syncthreads();

    float a = 6.28318530717958647692f * (1.0f/256.0f) * (float)h;
    float c1, s1; sincosf(a, &s1, &c1);
    float c2 = c1*c1 - s1*s1,  s2 = 2.f*s1*c1;
    float c3 = c2*c1 - s2*s1,  s3 = s2*c1 + c2*s1;
    float c4 = c2*c2 - s2*s2,  s4 = 2.f*s2*c2;
    float pc[8] = {1.f, c1, c2, c3,  c4,  c3,  c2,  c1};
    float ps[8] = {0.f, s1, s2, s3, -s4, -s3, -s2, -s1};

    float outv[8];
    #pragma unroll
    for (int ky = 0; ky < 4; ky++) {
        float zr = 0.f, zi = 0.f;
        #pragma unroll
        for (int kxi = 0; kxi < 8; kxi++) {
            float grv = gm[kxi*8 + ky*2], giv = gm[kxi*8 + ky*2 + 1];
            zr += grv*pc[kxi] - giv*ps[kxi];
            zi += grv*ps[kxi] + giv*pc[kxi];
        }
        if (ky == 0) outv[0] = zr * (1.f/131072.f);
        else { outv[ky*2-1] = zr * (1.f/65536.f);
               outv[ky*2  ] = zi * (1.f/65536.f); }
    }
    outv[7] = 0.f;

    float* zp = g_Z + ((b*HH + h)*CH + c)*8;
    #pragma unroll
    for (int j = 0; j < 8; j++) zp[j] = outv[j];
}

// ---------------------------------------------------------------------------
// K5: fused epilogue, f32x2 packed over OUTPUT-channel pairs.
// 1 pixel/thread, block = one row (256 px). Per c: recon hv in a register
// (1 LDG + 7 FMA), splat once, 32 FFMA2 against naturally-paired dec1
// weights from smem (no per-FMA splats, no hv smem tile).
// Static smem ~19 KB; target 2+ blocks/SM, 16 warps.
// ---------------------------------------------------------------------------
__global__ void __launch_bounds__(256, 2) k_final(
    const float* __restrict__ d1w, const float* __restrict__ d1b,
    const float* __restrict__ d2w, const float* __restrict__ d2b,
    float* __restrict__ out)
{
    __shared__ float zs[512];        // Z row, fi pre-negated
    __shared__ u64 wp[64*32];        // dec1 weight pairs: [c][o/2] = (w[o,c], w[o+1,c])
    __shared__ u64 b1p[32], w2p[32];

    int w = threadIdx.x, h = blockIdx.x, b = blockIdx.y;

    for (int idx = w; idx < 2048; idx += 256) {
        int c = idx & 63, op = idx >> 6;
        wp[c*32 + op] = pk2(d1w[(2*op)*64 + c], d1w[(2*op+1)*64 + c]);
    }
    if (w < 32) {
        b1p[w] = pk2(d1b[2*w], d1b[2*w+1]);
        w2p[w] = pk2(d2w[2*w], d2w[2*w+1]);
    }
    {
        const float* zrow = g_Z + (b*HH + h)*CH*8;
        for (int idx = w; idx < 512; idx += 256) {
            float v = zrow[idx];
            int j = idx & 7;
            if (j == 2 || j == 4 || j == 6) v = -v;
            zs[idx] = v;
        }
    }
    __syncthreads();

    float a = 6.28318530717958647692f * (1.0f/256.0f) * (float)w;
    float cy1, sy1; sincosf(a, &sy1, &cy1);
    float cy2 = cy1*cy1 - sy1*sy1, sy2 = 2.f*sy1*cy1;
    float cy3 = cy2*cy1 - sy2*sy1, sy3 = sy2*cy1 + cy2*sy1;

    u64 acc[32];
    #pragma unroll
    for (int k = 0; k < 32; k++) acc[k] = b1p[k];

    const float* h0p = g_h0 + b*CH*HW + h*WW + w;
    #pragma unroll 4
    for (int c = 0; c < 64; c++) {
        float h0v = h0p[c*HW];
        float4 za = *(const float4*)&zs[c*8];      // f0, fr1, -fi1, fr2
        float4 zb = *(const float4*)&zs[c*8 + 4];  // -fi2, fr3, -fi3, 0
        float hvv = h0v + za.x;
        hvv = fmaf(za.y, cy1, hvv);
        hvv = fmaf(za.z, sy1, hvv);
        hvv = fmaf(za.w, cy2, hvv);
        hvv = fmaf(zb.x, sy2, hvv);
        hvv = fmaf(zb.y, cy3, hvv);
        hvv = fmaf(zb.z, sy3, hvv);
        u64 hs = splat2(hvv);
        const ulonglong2* wrow = (const ulonglong2*)&wp[c*32];
        #pragma unroll
        for (int k2 = 0; k2 < 16; k2++) {
            ulonglong2 wv = wrow[k2];
            acc[k2*2]   = f2fma(hs, wv.x, acc[k2*2]);
            acc[k2*2+1] = f2fma(hs, wv.y, acc[k2*2+1]);
        }
    }

    u64 oacc = splat2(0.f);
    #pragma unroll
    for (int k = 0; k < 32; k++) {
        float2 v = upk2(acc[k]);
        u64 tv = pk2(tanhf(v.x), tanhf(v.y));
        oacc = f2fma(tv, w2p[k], oacc);
    }
    float2 o2 = upk2(oacc);
    out[b*HW + h*WW + w] = o2.x + o2.y + d2b[0];
}

extern "C" void kernel_launch(void* const* d_in, const int* in_sizes, int n_in,
                              void* d_out, int out_size)
{
    const float* x   = (const float*)d_in[0];
    const float* ew  = (const float*)d_in[1];
    const float* eb  = (const float*)d_in[2];
    const float* d1w = (const float*)d_in[3];
    const float* d1b = (const float*)d_in[4];
    const float* d2w = (const float*)d_in[5];
    const float* d2b = (const float*)d_in[6];
    const float* w1r = (const float*)d_in[7];
    const float* w1i = (const float*)d_in[8];
    const float* w2r = (const float*)d_in[9];
    const float* w2i = (const float*)d_in[10];
    float* out = (float*)d_out;

    cudaFuncSetAttribute(k_mix6, cudaFuncAttributeMaxDynamicSharedMemorySize, 65536);

    k_repack<<<32, 256>>>(w1r, w1i, w2r, w2i);
    k_encode<<<dim3(256, 8), 256>>>(x, ew, eb);
    k_project<<<dim3(64, 8), 256>>>();
    k_mix6<<<dim3(29, 8), 128, 65536>>>();
    k_ztable<<<dim3(64, 8), 256>>>();
    k_final<<<dim3(256, 8), 256>>>(d1w, d1b, d2w, d2b, out);
}